// round 2
// baseline (speedup 1.0000x reference)
#include <cuda_runtime.h>

// NF4 blockwise quant-dequant (blocksize 512).
// One warp per 512-element quant block: 32 lanes x 16 elements (4x float4).
// R2 change: per-element LDS LUT replaced by a pure-FP compare/select binary
// tree against immediate constants (15 FSETP + 15 FSEL), eliminating the L1
// shared-memory wavefront bottleneck seen in R1 ncu (L1=84%, DRAM=55.6%).

#define NQB_PER_CTA 8   // 8 warps per CTA, one quant-block each

// NF4 codebook (exact bitsandbytes constants)
#define C0  (-1.0f)
#define C1  (-0.6961928009986877f)
#define C2  (-0.5250730514526367f)
#define C3  (-0.39491748809814453f)
#define C4  (-0.28444138169288635f)
#define C5  (-0.18477343022823334f)
#define C6  (-0.09105003625154495f)
#define C7  (0.0f)
#define C8  (0.07958029955625534f)
#define C9  (0.16093020141124725f)
#define C10 (0.24611230194568634f)
#define C11 (0.33791524171829224f)
#define C12 (0.4407098591327667f)
#define C13 (0.5626170039176941f)
#define C14 (0.7229568362236023f)
#define C15 (1.0f)

// Decision boundaries: exact fp32 midpoints (folded at compile time in RN)
#define M0  ((C0  + C1 ) * 0.5f)
#define M1  ((C1  + C2 ) * 0.5f)
#define M2  ((C2  + C3 ) * 0.5f)
#define M3  ((C3  + C4 ) * 0.5f)
#define M4  ((C4  + C5 ) * 0.5f)
#define M5  ((C5  + C6 ) * 0.5f)
#define M6  ((C6  + C7 ) * 0.5f)
#define M7  ((C7  + C8 ) * 0.5f)
#define M8  ((C8  + C9 ) * 0.5f)
#define M9  ((C9  + C10) * 0.5f)
#define M10 ((C10 + C11) * 0.5f)
#define M11 ((C11 + C12) * 0.5f)
#define M12 ((C12 + C13) * 0.5f)
#define M13 ((C13 + C14) * 0.5f)
#define M14 ((C14 + C15) * 0.5f)

// NF4[idx] where idx = #{ MID[i] < xn }  (searchsorted, side='left')
__device__ __forceinline__ float nf4_pick(float xn) {
    return xn > M7
        ? (xn > M11
            ? (xn > M13 ? (xn > M14 ? C15 : C14) : (xn > M12 ? C13 : C12))
            : (xn > M9  ? (xn > M10 ? C11 : C10) : (xn > M8  ? C9  : C8)))
        : (xn > M3
            ? (xn > M5  ? (xn > M6  ? C7  : C6)  : (xn > M4  ? C5  : C4))
            : (xn > M1  ? (xn > M2  ? C3  : C2)  : (xn > M0  ? C1  : C0)));
}

__global__ __launch_bounds__(256) void nf4_qdq_kernel(
    const float* __restrict__ x, float* __restrict__ out, long long n_qb) {
    int warp = threadIdx.x >> 5;
    int lane = threadIdx.x & 31;
    long long qb = (long long)blockIdx.x * NQB_PER_CTA + warp;
    if (qb >= n_qb) return;   // warp-uniform exit; no barriers anywhere

    const float4* __restrict__ in4  = (const float4*)(x   + qb * 512);
    float4*       __restrict__ out4 = (float4*)      (out + qb * 512);

    // 16 elements per lane, 4x coalesced 128-bit loads (front-batched -> MLP=4)
    float4 v[4];
    #pragma unroll
    for (int i = 0; i < 4; i++) v[i] = in4[i * 32 + lane];

    // Blockwise absmax: register FMNMX(|.|) then warp butterfly
    float m = 0.0f;
    #pragma unroll
    for (int i = 0; i < 4; i++) {
        m = fmaxf(m, fabsf(v[i].x));
        m = fmaxf(m, fabsf(v[i].y));
        m = fmaxf(m, fabsf(v[i].z));
        m = fmaxf(m, fabsf(v[i].w));
    }
    #pragma unroll
    for (int s = 16; s; s >>= 1)
        m = fmaxf(m, __shfl_xor_sync(0xffffffffu, m, s));

    float absmax = m;
    float scale  = (absmax == 0.0f) ? 1.0f : absmax;
    float rs     = __frcp_rn(scale);   // once per warp; IEEE-RN reciprocal

    #pragma unroll
    for (int i = 0; i < 4; i++) {
        float4 r;
        r.x = nf4_pick(v[i].x * rs) * absmax;
        r.y = nf4_pick(v[i].y * rs) * absmax;
        r.z = nf4_pick(v[i].z * rs) * absmax;
        r.w = nf4_pick(v[i].w * rs) * absmax;
        out4[i * 32 + lane] = r;
    }
}

extern "C" void kernel_launch(void* const* d_in, const int* in_sizes, int n_in,
                              void* d_out, int out_size) {
    const float* x = (const float*)d_in[0];
    float* out = (float*)d_out;
    long long n = (long long)in_sizes[0];
    long long n_qb = n / 512;                 // n is a multiple of 512
    int grid = (int)((n_qb + NQB_PER_CTA - 1) / NQB_PER_CTA);
    nf4_qdq_kernel<<<grid, 256>>>(x, out, n_qb);
}

// round 3
// speedup vs baseline: 1.3172x; 1.3172x over previous
#include <cuda_runtime.h>

// NF4 blockwise quant-dequant (blocksize 512).
// One warp per 512-element quant block: 32 lanes x 16 elements (4x float4).
// R3: warp-register LUT. 32 buckets over [-1,1] (width 1/16 < min boundary gap
// 0.0805 -> at most one decision boundary per bucket). Lane k holds bucket k's
// (threshold, val_below, val_above), pre-scaled by absmax after the reduction.
// Per element: fma -> f2i -> clamp -> 3 indexed shuffles -> setp -> sel.
// No shared memory (R1 was L1-bound at 84%), no compare tree (R2 was ALU-bound
// at 78%).

#define NQB_PER_CTA 8

// NF4 codebook (exact bitsandbytes constants)
#define C0  (-1.0f)
#define C1  (-0.6961928009986877f)
#define C2  (-0.5250730514526367f)
#define C3  (-0.39491748809814453f)
#define C4  (-0.28444138169288635f)
#define C5  (-0.18477343022823334f)
#define C6  (-0.09105003625154495f)
#define C7  (0.0f)
#define C8  (0.07958029955625534f)
#define C9  (0.16093020141124725f)
#define C10 (0.24611230194568634f)
#define C11 (0.33791524171829224f)
#define C12 (0.4407098591327667f)
#define C13 (0.5626170039176941f)
#define C14 (0.7229568362236023f)
#define C15 (1.0f)

// Decision boundaries: exact fp32 midpoints (compile-time folded in RN)
#define MID(i)  ((CB[i] + CB[i + 1]) * 0.5f)

__device__ __constant__ const float CB_UNUSED = 0.0f;  // (no constant-mem loads in hot path)

__global__ __launch_bounds__(256) void nf4_qdq_kernel(
    const float* __restrict__ x, float* __restrict__ out, long long n_qb) {
    const float CB[16] = {C0, C1, C2, C3, C4, C5, C6, C7,
                          C8, C9, C10, C11, C12, C13, C14, C15};

    int warp = threadIdx.x >> 5;
    int lane = threadIdx.x & 31;
    long long qb = (long long)blockIdx.x * NQB_PER_CTA + warp;
    if (qb >= n_qb) return;   // warp-uniform; no barriers anywhere

    // ---- per-lane bucket table (bucket k == lane), normalized domain ----
    // Bucket k covers xn in [k/16 - 1, (k+1)/16 - 1).
    float lo = (float)lane * 0.0625f - 1.0f;
    float hi = lo + 0.0625f;

    // vlo_n = NF4[j], j = #{ midpoints < lo }  (codebook value at bucket start)
    float vlo_n = CB[0];
    #pragma unroll
    for (int i = 0; i < 15; i++)
        vlo_n = (MID(i) < lo) ? CB[i + 1] : vlo_n;

    // thr_n = the (unique) midpoint inside the bucket, else +inf; vhi_n = value above it
    float thr_n = __int_as_float(0x7f800000);
    float vhi_n = vlo_n;
    #pragma unroll
    for (int i = 0; i < 15; i++) {
        bool in_bucket = (MID(i) >= lo) && (MID(i) < hi);
        thr_n = in_bucket ? MID(i) : thr_n;
        vhi_n = in_bucket ? CB[i + 1] : vhi_n;
    }

    const float4* __restrict__ in4  = (const float4*)(x   + qb * 512);
    float4*       __restrict__ out4 = (float4*)      (out + qb * 512);

    // 16 elements per lane, 4x coalesced 128-bit loads (front-batched, MLP=4)
    float4 v[4];
    #pragma unroll
    for (int i = 0; i < 4; i++) v[i] = in4[i * 32 + lane];

    // Blockwise absmax: register FMNMX then warp butterfly (exact)
    float m = 0.0f;
    #pragma unroll
    for (int i = 0; i < 4; i++) {
        m = fmaxf(m, fabsf(v[i].x));
        m = fmaxf(m, fabsf(v[i].y));
        m = fmaxf(m, fabsf(v[i].z));
        m = fmaxf(m, fabsf(v[i].w));
    }
    #pragma unroll
    for (int s = 16; s; s >>= 1)
        m = fmaxf(m, __shfl_xor_sync(0xffffffffu, m, s));

    float absmax = m;
    float scale  = (absmax == 0.0f) ? 1.0f : absmax;
    float s16    = __frcp_rn(scale) * 16.0f;  // bucketing only; slop-tolerant

    // Scale tables into the raw-x domain (once per warp; inf*scale stays inf)
    float thr_s = thr_n * scale;    // compare x > thr_n*scale  ~  x/scale > thr_n
    float vlo_s = vlo_n * absmax;   // same RN mul as reference's NF4[idx]*absmax
    float vhi_s = vhi_n * absmax;

    #pragma unroll
    for (int i = 0; i < 4; i++) {
        float4 r;
        #pragma unroll
        for (int e = 0; e < 4; e++) {
            float xv = (&v[i].x)[e];
            float kf = fmaf(xv, s16, 16.0f);          // bucket in [0,32]
            int k = min((int)kf, 31);                 // trunc; tiny negatives -> 0
            float t = __shfl_sync(0xffffffffu, thr_s, k);
            float a = __shfl_sync(0xffffffffu, vlo_s, k);
            float b = __shfl_sync(0xffffffffu, vhi_s, k);
            (&r.x)[e] = (xv > t) ? b : a;
        }
        out4[i * 32 + lane] = r;
    }
}

extern "C" void kernel_launch(void* const* d_in, const int* in_sizes, int n_in,
                              void* d_out, int out_size) {
    const float* x = (const float*)d_in[0];
    float* out = (float*)d_out;
    long long n = (long long)in_sizes[0];
    long long n_qb = n / 512;                 // n is a multiple of 512
    int grid = (int)((n_qb + NQB_PER_CTA - 1) / NQB_PER_CTA);
    nf4_qdq_kernel<<<grid, 256>>>(x, out, n_qb);
}